// round 16
// baseline (speedup 1.0000x reference)
#include <cuda_runtime.h>
#include <cuda_fp16.h>
#include <cstdint>

#define DIMC 512
#define HEADS 16
#define HD 32
#define SW 49
#define NWIN 64
#define BWIN 2048
#define TOKENS (BWIN * SW)   // 100352

#define SAH 72                 // GEMM smem row stride in halfs (144B; ldsm conflict-free)
#define STAGES 2
#define BUFH (128 * SAH)       // halfs per stage per matrix (9216)
#define GEMM_SMEM (STAGES * 2 * BUFH * 2)   // 73728 bytes -> 3 CTAs/SM

#define ASA 56                 // attention smem row stride in halfs
#define MBROW 52               // padded mb row (floats)
#define MBTILE (SW * MBROW)

// pre-pass fused grid split
#define NCVT (TOKENS * DIMC / 4 / 256)     // 50176 blocks
#define NTQ  (48 * 16)                      // tconv qkv_w blocks
#define NTP  (16 * 16)                      // tconv proj_w blocks
#define NMB  (NWIN * HEADS)                 // mb blocks

// Scratch (static device globals; no runtime allocation)
__device__ __half g_qkvh[(size_t)TOKENS * 3 * DIMC];
__device__ __half g_atth[(size_t)TOKENS * DIMC];
__device__ __half g_xh[(size_t)TOKENS * DIMC];
__device__ __half g_wtqh[(size_t)(3 * DIMC) * DIMC];
__device__ __half g_wtph[(size_t)DIMC * DIMC];
__device__ float  g_mb[(size_t)NWIN * HEADS * MBTILE + 64];

// ---------------------------------------------------------------------------
__device__ __forceinline__ void mma_f16(float* d, const unsigned* a, const unsigned* b) {
    asm volatile(
        "mma.sync.aligned.m16n8k16.row.col.f32.f16.f16.f32 "
        "{%0,%1,%2,%3}, {%4,%5,%6,%7}, {%8,%9}, {%0,%1,%2,%3};"
        : "+f"(d[0]), "+f"(d[1]), "+f"(d[2]), "+f"(d[3])
        : "r"(a[0]), "r"(a[1]), "r"(a[2]), "r"(a[3]), "r"(b[0]), "r"(b[1]));
}

__device__ __forceinline__ void ldsm4(unsigned& r0, unsigned& r1,
                                      unsigned& r2, unsigned& r3, uint32_t addr) {
    asm volatile("ldmatrix.sync.aligned.m8n8.x4.shared.b16 {%0,%1,%2,%3}, [%4];"
                 : "=r"(r0), "=r"(r1), "=r"(r2), "=r"(r3) : "r"(addr));
}

__device__ __forceinline__ void ldsm4t(unsigned& r0, unsigned& r1,
                                       unsigned& r2, unsigned& r3, uint32_t addr) {
    asm volatile("ldmatrix.sync.aligned.m8n8.x4.trans.shared.b16 {%0,%1,%2,%3}, [%4];"
                 : "=r"(r0), "=r"(r1), "=r"(r2), "=r"(r3) : "r"(addr));
}

__device__ __forceinline__ void cpasync16(uint32_t dst, const void* src) {
    asm volatile("cp.async.cg.shared.global [%0], [%1], 16;" :: "r"(dst), "l"(src));
}

__device__ __forceinline__ unsigned packh2(float lo, float hi) {
    __half2 t = __floats2half2_rn(lo, hi);
    return *(unsigned*)&t;
}

// exp on the FMA/ALU pipes (no MUFU)
__device__ __forceinline__ float fast_exp(float z) {
    z = fmaxf(z, -80.f);
    float y = z * 1.44269504088896f;
    int i = __float2int_rn(y);
    float f = y - (float)i;
    float p = 0.0013333558146f;
    p = fmaf(p, f, 0.0096181291076f);
    p = fmaf(p, f, 0.0555041086648f);
    p = fmaf(p, f, 0.2402265069591f);
    p = fmaf(p, f, 0.6931471805599f);
    p = fmaf(p, f, 1.0f);
    return p * __int_as_float((i + 127) << 23);
}

// ---------------------------------------------------------------------------
// Fused pre-pass: cvt x -> fp16 | transpose+cvt both weights | mb table.
// All sub-tasks use 256 threads; dispatch on blockIdx.x ranges.
// ---------------------------------------------------------------------------
__global__ __launch_bounds__(256) void prepass_kernel(
        const float4* __restrict__ x4,
        const float* __restrict__ qkv_w, const float* __restrict__ proj_w,
        const float* __restrict__ mask, const float* __restrict__ bias_table,
        const int* __restrict__ rel_idx) {
    const int blk = blockIdx.x;
    const int tid = threadIdx.x;

    if (blk < NCVT) {
        // x fp32 -> fp16
        const int i = blk * 256 + tid;
        float4 v = x4[i];
        __half2* dst = (__half2*)g_xh;
        dst[2 * i]     = __floats2half2_rn(v.x, v.y);
        dst[2 * i + 1] = __floats2half2_rn(v.z, v.w);
    } else if (blk < NCVT + NTQ + NTP) {
        // weight transpose + cvt: Wt[n*K+k] = fp16(W[k*N+n]), 32x32 tiles
        const bool isQ = blk < NCVT + NTQ;
        const int b2 = isQ ? (blk - NCVT) : (blk - NCVT - NTQ);
        const int NN = isQ ? (3 * DIMC) : DIMC;
        const float* W = isQ ? qkv_w : proj_w;
        __half* Wt = isQ ? g_wtqh : g_wtph;
        const int nblk = NN / 32;
        const int n0 = (b2 % nblk) * 32, k0 = (b2 / nblk) * 32;
        const int tx = tid & 31, ty = tid >> 5;   // 32 x 8

        __shared__ float t[32][33];
#pragma unroll
        for (int r = 0; r < 32; r += 8)
            t[ty + r][tx] = W[(size_t)(k0 + ty + r) * NN + n0 + tx];
        __syncthreads();
#pragma unroll
        for (int r = 0; r < 32; r += 8)
            Wt[(size_t)(n0 + ty + r) * DIMC + k0 + tx] = __float2half_rn(t[tx][ty + r]);
    } else {
        // fused mask + bias, rows padded to MBROW
        const int wh = blk - NCVT - NTQ - NTP;
        const int w = wh / HEADS, h = wh % HEADS;
        const float* mrow = mask + (size_t)w * SW * SW;
        float* out = g_mb + (size_t)wh * MBTILE;
        for (int e = tid; e < SW * SW; e += 256) {
            const int i = e / SW, j = e % SW;
            out[i * MBROW + j] = mrow[e] + bias_table[rel_idx[e] * HEADS + h];
        }
    }
}

// ---------------------------------------------------------------------------
// C[M,N] = A[M,K] @ Wt[N,K]^T + bias[N]   (fp16 operands, fp32 accumulate)
// Block tile 128x128, k-tile 64, 128 threads, 4 warps (2m x 2n), warp 64x64.
// 2-stage cp.async pipeline (double buffer), 3 CTAs/SM, K fully unrolled.
// ---------------------------------------------------------------------------
template <typename OutT, int KK>
__global__ __launch_bounds__(128, 3) void gemm_f16_kernel(
        const __half* __restrict__ A, const __half* __restrict__ Wt,
        const float* __restrict__ bias, OutT* __restrict__ C,
        int M, int N) {
    extern __shared__ __half sh[];
    __half* As = sh;
    __half* Bs = sh + STAGES * BUFH;

    const int tid = threadIdx.x;
    const int lane = tid & 31;
    const int wid = tid >> 5;
    const int wm = (wid >> 1) * 64;
    const int wn = (wid & 1) * 64;
    const int m0 = blockIdx.y * 128;
    const int n0 = blockIdx.x * 128;

    const uint32_t asA = (uint32_t)__cvta_generic_to_shared(As);
    const uint32_t asB = (uint32_t)__cvta_generic_to_shared(Bs);

    const int rowoff = ((lane >> 3) & 1) * 8 + (lane & 7);
    const unsigned aBaseH = (unsigned)((wm + rowoff) * SAH + (lane >> 4) * 8);
    const unsigned bBaseH = (unsigned)((wn + ((lane >> 4) & 1) * 8 + (lane & 7)) * SAH
                                       + ((lane >> 3) & 1) * 8);

    float acc[4][8][4];
#pragma unroll
    for (int mt = 0; mt < 4; mt++)
#pragma unroll
        for (int nt = 0; nt < 8; nt++)
#pragma unroll
            for (int r = 0; r < 4; r++) acc[mt][nt][r] = 0.f;

    constexpr int NITER = KK >> 6;   // k-tiles of 64

#define ISSUE_TILE(t, s)                                                             \
    do {                                                                             \
        const int k0_ = (t) << 6;                                                    \
        _Pragma("unroll")                                                            \
        for (int i = 0; i < 8; i++) {                                                \
            const int idx = tid + i * 128;                                           \
            const int row = idx >> 3, seg = idx & 7;                                 \
            const uint32_t doff = (uint32_t)((s) * BUFH + row * SAH + seg * 8) * 2u; \
            cpasync16(asA + doff, &A[(size_t)(m0 + row) * KK + k0_ + seg * 8]);      \
            cpasync16(asB + doff, &Wt[(size_t)(n0 + row) * KK + k0_ + seg * 8]);     \
        }                                                                            \
        asm volatile("cp.async.commit_group;");                                      \
    } while (0)

    ISSUE_TILE(0, 0);

#pragma unroll
    for (int it = 0; it < NITER; it++) {
        asm volatile("cp.async.wait_group 0;");
        __syncthreads();

        if (it + 1 < NITER) ISSUE_TILE(it + 1, (it + 1) & 1);

        const int buf = it & 1;
#pragma unroll
        for (int ks = 0; ks < 4; ks++) {
            unsigned afr[4][4];
#pragma unroll
            for (int mt = 0; mt < 4; mt++) {
                uint32_t addr = asA +
                    ((unsigned)(buf * BUFH + mt * 16 * SAH + ks * 16) + aBaseH) * 2u;
                ldsm4(afr[mt][0], afr[mt][1], afr[mt][2], afr[mt][3], addr);
            }
            unsigned bfr[8][2];
#pragma unroll
            for (int p = 0; p < 4; p++) {
                uint32_t addr = asB +
                    ((unsigned)(buf * BUFH + p * 16 * SAH + ks * 16) + bBaseH) * 2u;
                unsigned r0, r1, r2, r3;
                ldsm4(r0, r1, r2, r3, addr);
                bfr[2 * p][0] = r0;     bfr[2 * p][1] = r1;
                bfr[2 * p + 1][0] = r2; bfr[2 * p + 1][1] = r3;
            }
#pragma unroll
            for (int mt = 0; mt < 4; mt++)
#pragma unroll
                for (int nt2 = 0; nt2 < 8; nt2++)
                    mma_f16(acc[mt][nt2], afr[mt], bfr[nt2]);
        }
    }
#undef ISSUE_TILE

#pragma unroll
    for (int mt = 0; mt < 4; mt++) {
        const int r = m0 + wm + mt * 16 + (lane >> 2);
#pragma unroll
        for (int nt = 0; nt < 8; nt++) {
            const int c = n0 + wn + nt * 8 + ((lane & 3) << 1);
            const float b0 = bias[c], b1 = bias[c + 1];
            if constexpr (sizeof(OutT) == 4) {
                *(float2*)&C[(size_t)r * N + c] =
                    make_float2(acc[mt][nt][0] + b0, acc[mt][nt][1] + b1);
                *(float2*)&C[(size_t)(r + 8) * N + c] =
                    make_float2(acc[mt][nt][2] + b0, acc[mt][nt][3] + b1);
            } else {
                *(unsigned*)&C[(size_t)r * N + c] =
                    packh2(acc[mt][nt][0] + b0, acc[mt][nt][1] + b1);
                *(unsigned*)&C[(size_t)(r + 8) * N + c] =
                    packh2(acc[mt][nt][2] + b0, acc[mt][nt][3] + b1);
            }
        }
    }
}

// ---------------------------------------------------------------------------
// Tensor-core attention: one block per (window b, head h), 128 threads.
// q/k/v and mb staged via cp.async (single group); pad rows zeroed by STS.
// (R15 validated — unchanged.)
// ---------------------------------------------------------------------------
__global__ __launch_bounds__(128) void attn_mma_kernel() {
    __shared__ __half Qs[64 * ASA];
    __shared__ __half Ks[64 * ASA];
    __shared__ __half Vs[64 * ASA];
    __shared__ float  Mbs[MBTILE];

    const int bh = blockIdx.x;
    const int b = bh >> 4;
    const int h = bh & 15;
    const int tid = threadIdx.x;
    const int lane = tid & 31;
    const int w = tid >> 5;
    const float scale = 0.17677669529663689f;

    const uint32_t sQ = (uint32_t)__cvta_generic_to_shared(Qs);
    const uint32_t sK = (uint32_t)__cvta_generic_to_shared(Ks);
    const uint32_t sV = (uint32_t)__cvta_generic_to_shared(Vs);
    const uint32_t sM = (uint32_t)__cvta_generic_to_shared(Mbs);

    {
        const char* src = (const char*)(g_mb + (size_t)((b & (NWIN - 1)) * HEADS + h) * MBTILE);
        for (int i = tid; i < (MBTILE * 4) / 16; i += 128)
            cpasync16(sM + i * 16, src + i * 16);
    }

    {
        const __half* src = g_qkvh + (size_t)b * SW * (3 * DIMC) + h * HD;
#pragma unroll
        for (int i = 0; i < 2; i++) {
            const int e = tid + i * 128;
            const int row = e >> 2, seg = (e & 3) * 8;
            const uint32_t off = (uint32_t)(row * ASA + seg) * 2u;
            if (row < SW) {
                const __half* p = src + (size_t)row * (3 * DIMC) + seg;
                cpasync16(sQ + off, p);
                cpasync16(sK + off, p + DIMC);
                cpasync16(sV + off, p + 2 * DIMC);
            } else {
                const uint4 z = {0, 0, 0, 0};
                *(uint4*)&Qs[row * ASA + seg] = z;
                *(uint4*)&Ks[row * ASA + seg] = z;
                *(uint4*)&Vs[row * ASA + seg] = z;
            }
        }
    }
    asm volatile("cp.async.commit_group;");
    asm volatile("cp.async.wait_group 0;");
    __syncthreads();

    const int rowoff = ((lane >> 3) & 1) * 8 + (lane & 7);
    const unsigned aBase = (unsigned)((w * 16 + rowoff) * ASA + (lane >> 4) * 8);
    const unsigned bBase = (unsigned)((((lane >> 4) & 1) * 8 + (lane & 7)) * ASA
                                      + ((lane >> 3) & 1) * 8);

    float sc[8][4];
#pragma unroll
    for (int nb = 0; nb < 8; nb++)
#pragma unroll
        for (int r = 0; r < 4; r++) sc[nb][r] = 0.f;

#pragma unroll
    for (int ks = 0; ks < 2; ks++) {
        unsigned afr[4];
        ldsm4(afr[0], afr[1], afr[2], afr[3], sQ + (aBase + ks * 16) * 2u);
        unsigned bfr[8][2];
#pragma unroll
        for (int p = 0; p < 4; p++) {
            unsigned r0, r1, r2, r3;
            ldsm4(r0, r1, r2, r3, sK + ((unsigned)(p * 16 * ASA + ks * 16) + bBase) * 2u);
            bfr[2 * p][0] = r0;     bfr[2 * p][1] = r1;
            bfr[2 * p + 1][0] = r2; bfr[2 * p + 1][1] = r3;
        }
#pragma unroll
        for (int nb = 0; nb < 8; nb++) mma_f16(sc[nb], afr, bfr[nb]);
    }

    const int rA = w * 16 + (lane >> 2);
    const int rB = rA + 8;

    float mxA = -1e30f, mxB = -1e30f;
#pragma unroll
    for (int nb = 0; nb < 8; nb++) {
        const int c0 = nb * 8 + (lane & 3) * 2;
        const bool vA0 = (rA < SW) && (c0 < SW), vA1 = (rA < SW) && (c0 + 1 < SW);
        const bool vB0 = (rB < SW) && (c0 < SW), vB1 = (rB < SW) && (c0 + 1 < SW);
        sc[nb][0] = vA0 ? fmaf(sc[nb][0], scale, Mbs[rA * MBROW + c0])     : -1e30f;
        sc[nb][1] = vA1 ? fmaf(sc[nb][1], scale, Mbs[rA * MBROW + c0 + 1]) : -1e30f;
        sc[nb][2] = vB0 ? fmaf(sc[nb][2], scale, Mbs[rB * MBROW + c0])     : -1e30f;
        sc[nb][3] = vB1 ? fmaf(sc[nb][3], scale, Mbs[rB * MBROW + c0 + 1]) : -1e30f;
        mxA = fmaxf(mxA, fmaxf(sc[nb][0], sc[nb][1]));
        mxB = fmaxf(mxB, fmaxf(sc[nb][2], sc[nb][3]));
    }
    mxA = fmaxf(mxA, __shfl_xor_sync(0xFFFFFFFFu, mxA, 1));
    mxA = fmaxf(mxA, __shfl_xor_sync(0xFFFFFFFFu, mxA, 2));
    mxB = fmaxf(mxB, __shfl_xor_sync(0xFFFFFFFFu, mxB, 1));
    mxB = fmaxf(mxB, __shfl_xor_sync(0xFFFFFFFFu, mxB, 2));

    float sA = 0.f, sB = 0.f;
#pragma unroll
    for (int nb = 0; nb < 8; nb++) {
        sc[nb][0] = fast_exp(sc[nb][0] - mxA);
        sc[nb][1] = fast_exp(sc[nb][1] - mxA);
        sc[nb][2] = fast_exp(sc[nb][2] - mxB);
        sc[nb][3] = fast_exp(sc[nb][3] - mxB);
        sA += sc[nb][0] + sc[nb][1];
        sB += sc[nb][2] + sc[nb][3];
    }
    sA += __shfl_xor_sync(0xFFFFFFFFu, sA, 1);
    sA += __shfl_xor_sync(0xFFFFFFFFu, sA, 2);
    sB += __shfl_xor_sync(0xFFFFFFFFu, sB, 1);
    sB += __shfl_xor_sync(0xFFFFFFFFu, sB, 2);
    const float invA = __fdividef(1.f, sA);
    const float invB = __fdividef(1.f, sB);

    float o[4][4];
#pragma unroll
    for (int db = 0; db < 4; db++)
#pragma unroll
        for (int r = 0; r < 4; r++) o[db][r] = 0.f;

#pragma unroll
    for (int j = 0; j < 4; j++) {
        unsigned pf[4];
        pf[0] = packh2(sc[2 * j][0] * invA, sc[2 * j][1] * invA);
        pf[1] = packh2(sc[2 * j][2] * invB, sc[2 * j][3] * invB);
        pf[2] = packh2(sc[2 * j + 1][0] * invA, sc[2 * j + 1][1] * invA);
        pf[3] = packh2(sc[2 * j + 1][2] * invB, sc[2 * j + 1][3] * invB);

        const unsigned vrow = (unsigned)(16 * j + (lane & 7) + 8 * ((lane >> 3) & 1));
        unsigned vf[4][2];
#pragma unroll
        for (int nb2 = 0; nb2 < 2; nb2++) {
            unsigned r0, r1, r2, r3;
            uint32_t addr = sV + (vrow * ASA + nb2 * 16 + ((lane >> 4) & 1) * 8) * 2u;
            ldsm4t(r0, r1, r2, r3, addr);
            vf[2 * nb2][0] = r0;     vf[2 * nb2][1] = r1;
            vf[2 * nb2 + 1][0] = r2; vf[2 * nb2 + 1][1] = r3;
        }
#pragma unroll
        for (int db = 0; db < 4; db++) mma_f16(o[db], pf, vf[db]);
    }

    if (rA < SW) {
        __half* out = g_atth + ((size_t)(b * SW + rA)) * DIMC + h * HD;
#pragma unroll
        for (int db = 0; db < 4; db++)
            *(unsigned*)&out[db * 8 + (lane & 3) * 2] = packh2(o[db][0], o[db][1]);
    }
    if (rB < SW) {
        __half* out = g_atth + ((size_t)(b * SW + rB)) * DIMC + h * HD;
#pragma unroll
        for (int db = 0; db < 4; db++)
            *(unsigned*)&out[db * 8 + (lane & 3) * 2] = packh2(o[db][2], o[db][3]);
    }
}

// ---------------------------------------------------------------------------
extern "C" void kernel_launch(void* const* d_in, const int* in_sizes, int n_in,
                              void* d_out, int out_size) {
    const float* x          = (const float*)d_in[0];
    const float* mask       = (const float*)d_in[1];
    const float* qkv_w      = (const float*)d_in[2];
    const float* qkv_b      = (const float*)d_in[3];
    const float* proj_w     = (const float*)d_in[4];
    const float* proj_b     = (const float*)d_in[5];
    const float* bias_table = (const float*)d_in[6];
    const int*   rel_idx    = (const int*)d_in[7];

    static __half* qkvh_ptr = nullptr;
    static __half* atth_ptr = nullptr;
    static __half* xh_ptr = nullptr;
    static __half* wtqh_ptr = nullptr;
    static __half* wtph_ptr = nullptr;
    if (!qkvh_ptr) {
        cudaGetSymbolAddress((void**)&qkvh_ptr, g_qkvh);
        cudaGetSymbolAddress((void**)&atth_ptr, g_atth);
        cudaGetSymbolAddress((void**)&xh_ptr, g_xh);
        cudaGetSymbolAddress((void**)&wtqh_ptr, g_wtqh);
        cudaGetSymbolAddress((void**)&wtph_ptr, g_wtph);
        cudaFuncSetAttribute((const void*)gemm_f16_kernel<__half, DIMC>,
                             cudaFuncAttributeMaxDynamicSharedMemorySize, GEMM_SMEM);
        cudaFuncSetAttribute((const void*)gemm_f16_kernel<float, DIMC>,
                             cudaFuncAttributeMaxDynamicSharedMemorySize, GEMM_SMEM);
    }

    // 0) fused pre-pass
    prepass_kernel<<<NCVT + NTQ + NTP + NMB, 256>>>(
        (const float4*)x, qkv_w, proj_w, mask, bias_table, rel_idx);

    // 1) QKV projection -> fp16
    gemm_f16_kernel<__half, DIMC><<<dim3(3 * DIMC / 128, TOKENS / 128), 128, GEMM_SMEM>>>(
        xh_ptr, wtqh_ptr, qkv_b, qkvh_ptr, TOKENS, 3 * DIMC);

    // 2) Tensor-core windowed attention
    attn_mma_kernel<<<BWIN * HEADS, 128>>>();

    // 3) Output projection -> fp32 d_out
    gemm_f16_kernel<float, DIMC><<<dim3(DIMC / 128, TOKENS / 128), 128, GEMM_SMEM>>>(
        atth_ptr, wtph_ptr, proj_b, (float*)d_out, TOKENS, DIMC);
}

// round 17
// speedup vs baseline: 1.2357x; 1.2357x over previous
#include <cuda_runtime.h>
#include <cuda_fp16.h>
#include <cstdint>

#define DIMC 512
#define HEADS 16
#define HD 32
#define SW 49
#define NWIN 64
#define BWIN 2048
#define TOKENS (BWIN * SW)   // 100352

#define SAH 72                 // GEMM smem row stride in halfs (144B; ldsm conflict-free)
#define STAGES 3
#define BUFH (128 * SAH)       // halfs per stage per matrix (9216)
#define GEMM_SMEM (STAGES * 2 * BUFH * 2)   // 110592 bytes -> 2 CTAs/SM

#define ASA 56                 // attention smem row stride in halfs
#define MBROW 52               // padded mb row (floats)
#define MBTILE (SW * MBROW)

// pre-pass fused grid split
#define NCVT (TOKENS * DIMC / 4 / 256)     // 50176 blocks
#define NTQ  (48 * 16)                      // tconv qkv_w blocks
#define NTP  (16 * 16)                      // tconv proj_w blocks
#define NMB  (NWIN * HEADS)                 // mb blocks

// Scratch (static device globals; no runtime allocation)
__device__ __half g_qkvh[(size_t)TOKENS * 3 * DIMC];
__device__ __half g_atth[(size_t)TOKENS * DIMC];
__device__ __half g_xh[(size_t)TOKENS * DIMC];
__device__ __half g_wtqh[(size_t)(3 * DIMC) * DIMC];
__device__ __half g_wtph[(size_t)DIMC * DIMC];
__device__ float  g_mb[(size_t)NWIN * HEADS * MBTILE + 64];

// ---------------------------------------------------------------------------
__device__ __forceinline__ void mma_f16(float* d, const unsigned* a, const unsigned* b) {
    asm volatile(
        "mma.sync.aligned.m16n8k16.row.col.f32.f16.f16.f32 "
        "{%0,%1,%2,%3}, {%4,%5,%6,%7}, {%8,%9}, {%0,%1,%2,%3};"
        : "+f"(d[0]), "+f"(d[1]), "+f"(d[2]), "+f"(d[3])
        : "r"(a[0]), "r"(a[1]), "r"(a[2]), "r"(a[3]), "r"(b[0]), "r"(b[1]));
}

__device__ __forceinline__ void ldsm4(unsigned& r0, unsigned& r1,
                                      unsigned& r2, unsigned& r3, uint32_t addr) {
    asm volatile("ldmatrix.sync.aligned.m8n8.x4.shared.b16 {%0,%1,%2,%3}, [%4];"
                 : "=r"(r0), "=r"(r1), "=r"(r2), "=r"(r3) : "r"(addr));
}

__device__ __forceinline__ void ldsm4t(unsigned& r0, unsigned& r1,
                                       unsigned& r2, unsigned& r3, uint32_t addr) {
    asm volatile("ldmatrix.sync.aligned.m8n8.x4.trans.shared.b16 {%0,%1,%2,%3}, [%4];"
                 : "=r"(r0), "=r"(r1), "=r"(r2), "=r"(r3) : "r"(addr));
}

__device__ __forceinline__ void cpasync16(uint32_t dst, const void* src) {
    asm volatile("cp.async.cg.shared.global [%0], [%1], 16;" :: "r"(dst), "l"(src));
}

__device__ __forceinline__ unsigned packh2(float lo, float hi) {
    __half2 t = __floats2half2_rn(lo, hi);
    return *(unsigned*)&t;
}

// exp on the FMA/ALU pipes (no MUFU)
__device__ __forceinline__ float fast_exp(float z) {
    z = fmaxf(z, -80.f);
    float y = z * 1.44269504088896f;
    int i = __float2int_rn(y);
    float f = y - (float)i;
    float p = 0.0013333558146f;
    p = fmaf(p, f, 0.0096181291076f);
    p = fmaf(p, f, 0.0555041086648f);
    p = fmaf(p, f, 0.2402265069591f);
    p = fmaf(p, f, 0.6931471805599f);
    p = fmaf(p, f, 1.0f);
    return p * __int_as_float((i + 127) << 23);
}

// ---------------------------------------------------------------------------
// Fused pre-pass: cvt x -> fp16 | transpose+cvt both weights | mb table.
// ---------------------------------------------------------------------------
__global__ __launch_bounds__(256) void prepass_kernel(
        const float4* __restrict__ x4,
        const float* __restrict__ qkv_w, const float* __restrict__ proj_w,
        const float* __restrict__ mask, const float* __restrict__ bias_table,
        const int* __restrict__ rel_idx) {
    const int blk = blockIdx.x;
    const int tid = threadIdx.x;

    if (blk < NCVT) {
        const int i = blk * 256 + tid;
        float4 v = x4[i];
        __half2* dst = (__half2*)g_xh;
        dst[2 * i]     = __floats2half2_rn(v.x, v.y);
        dst[2 * i + 1] = __floats2half2_rn(v.z, v.w);
    } else if (blk < NCVT + NTQ + NTP) {
        const bool isQ = blk < NCVT + NTQ;
        const int b2 = isQ ? (blk - NCVT) : (blk - NCVT - NTQ);
        const int NN = isQ ? (3 * DIMC) : DIMC;
        const float* W = isQ ? qkv_w : proj_w;
        __half* Wt = isQ ? g_wtqh : g_wtph;
        const int nblk = NN / 32;
        const int n0 = (b2 % nblk) * 32, k0 = (b2 / nblk) * 32;
        const int tx = tid & 31, ty = tid >> 5;   // 32 x 8

        __shared__ float t[32][33];
#pragma unroll
        for (int r = 0; r < 32; r += 8)
            t[ty + r][tx] = W[(size_t)(k0 + ty + r) * NN + n0 + tx];
        __syncthreads();
#pragma unroll
        for (int r = 0; r < 32; r += 8)
            Wt[(size_t)(n0 + ty + r) * DIMC + k0 + tx] = __float2half_rn(t[tx][ty + r]);
    } else {
        const int wh = blk - NCVT - NTQ - NTP;
        const int w = wh / HEADS, h = wh % HEADS;
        const float* mrow = mask + (size_t)w * SW * SW;
        float* out = g_mb + (size_t)wh * MBTILE;
        for (int e = tid; e < SW * SW; e += 256) {
            const int i = e / SW, j = e % SW;
            out[i * MBROW + j] = mrow[e] + bias_table[rel_idx[e] * HEADS + h];
        }
    }
}

// ---------------------------------------------------------------------------
// C[M,N] = A[M,K] @ Wt[N,K]^T + bias[N]   (fp16 operands, fp32 accumulate)
// Block tile 128x128, k-tile 64, 128 threads, 4 warps (2m x 2n), warp 64x64.
// 3-stage cp.async pipeline, wait_group 1, 2 CTAs/SM, K fully unrolled.
// (R15-validated configuration.)
// ---------------------------------------------------------------------------
template <typename OutT, int KK>
__global__ __launch_bounds__(128, 2) void gemm_f16_kernel(
        const __half* __restrict__ A, const __half* __restrict__ Wt,
        const float* __restrict__ bias, OutT* __restrict__ C,
        int M, int N) {
    extern __shared__ __half sh[];
    __half* As = sh;
    __half* Bs = sh + STAGES * BUFH;

    const int tid = threadIdx.x;
    const int lane = tid & 31;
    const int wid = tid >> 5;
    const int wm = (wid >> 1) * 64;
    const int wn = (wid & 1) * 64;
    const int m0 = blockIdx.y * 128;
    const int n0 = blockIdx.x * 128;

    const uint32_t asA = (uint32_t)__cvta_generic_to_shared(As);
    const uint32_t asB = (uint32_t)__cvta_generic_to_shared(Bs);

    const int rowoff = ((lane >> 3) & 1) * 8 + (lane & 7);
    const unsigned aBaseH = (unsigned)((wm + rowoff) * SAH + (lane >> 4) * 8);
    const unsigned bBaseH = (unsigned)((wn + ((lane >> 4) & 1) * 8 + (lane & 7)) * SAH
                                       + ((lane >> 3) & 1) * 8);

    float acc[4][8][4];
#pragma unroll
    for (int mt = 0; mt < 4; mt++)
#pragma unroll
        for (int nt = 0; nt < 8; nt++)
#pragma unroll
            for (int r = 0; r < 4; r++) acc[mt][nt][r] = 0.f;

    constexpr int NITER = KK >> 6;   // k-tiles of 64

#define ISSUE_TILE(t, s)                                                             \
    do {                                                                             \
        const int k0_ = (t) << 6;                                                    \
        _Pragma("unroll")                                                            \
        for (int i = 0; i < 8; i++) {                                                \
            const int idx = tid + i * 128;                                           \
            const int row = idx >> 3, seg = idx & 7;                                 \
            const uint32_t doff = (uint32_t)((s) * BUFH + row * SAH + seg * 8) * 2u; \
            cpasync16(asA + doff, &A[(size_t)(m0 + row) * KK + k0_ + seg * 8]);      \
            cpasync16(asB + doff, &Wt[(size_t)(n0 + row) * KK + k0_ + seg * 8]);     \
        }                                                                            \
        asm volatile("cp.async.commit_group;");                                      \
    } while (0)

    ISSUE_TILE(0, 0);
    ISSUE_TILE(1, 1);

#pragma unroll
    for (int it = 0; it < NITER; it++) {
        asm volatile("cp.async.wait_group 1;");
        __syncthreads();

        const int nt_ = it + 2;
        if (nt_ < NITER) {
            ISSUE_TILE(nt_, nt_ % 3);
        } else {
            asm volatile("cp.async.commit_group;");
        }

        const int buf = it % 3;
#pragma unroll
        for (int ks = 0; ks < 4; ks++) {
            unsigned afr[4][4];
#pragma unroll
            for (int mt = 0; mt < 4; mt++) {
                uint32_t addr = asA +
                    ((unsigned)(buf * BUFH + mt * 16 * SAH + ks * 16) + aBaseH) * 2u;
                ldsm4(afr[mt][0], afr[mt][1], afr[mt][2], afr[mt][3], addr);
            }
            unsigned bfr[8][2];
#pragma unroll
            for (int p = 0; p < 4; p++) {
                uint32_t addr = asB +
                    ((unsigned)(buf * BUFH + p * 16 * SAH + ks * 16) + bBaseH) * 2u;
                unsigned r0, r1, r2, r3;
                ldsm4(r0, r1, r2, r3, addr);
                bfr[2 * p][0] = r0;     bfr[2 * p][1] = r1;
                bfr[2 * p + 1][0] = r2; bfr[2 * p + 1][1] = r3;
            }
#pragma unroll
            for (int mt = 0; mt < 4; mt++)
#pragma unroll
                for (int nt2 = 0; nt2 < 8; nt2++)
                    mma_f16(acc[mt][nt2], afr[mt], bfr[nt2]);
        }
    }
#undef ISSUE_TILE

#pragma unroll
    for (int mt = 0; mt < 4; mt++) {
        const int r = m0 + wm + mt * 16 + (lane >> 2);
#pragma unroll
        for (int nt = 0; nt < 8; nt++) {
            const int c = n0 + wn + nt * 8 + ((lane & 3) << 1);
            const float b0 = bias[c], b1 = bias[c + 1];
            if constexpr (sizeof(OutT) == 4) {
                *(float2*)&C[(size_t)r * N + c] =
                    make_float2(acc[mt][nt][0] + b0, acc[mt][nt][1] + b1);
                *(float2*)&C[(size_t)(r + 8) * N + c] =
                    make_float2(acc[mt][nt][2] + b0, acc[mt][nt][3] + b1);
            } else {
                *(unsigned*)&C[(size_t)r * N + c] =
                    packh2(acc[mt][nt][0] + b0, acc[mt][nt][1] + b1);
                *(unsigned*)&C[(size_t)(r + 8) * N + c] =
                    packh2(acc[mt][nt][2] + b0, acc[mt][nt][3] + b1);
            }
        }
    }
}

// ---------------------------------------------------------------------------
// Tensor-core attention: one block per (window b, head h), 128 threads.
// q/k/v and mb staged via cp.async; pad rows zeroed by STS. (R15-validated.)
// ---------------------------------------------------------------------------
__global__ __launch_bounds__(128) void attn_mma_kernel() {
    __shared__ __half Qs[64 * ASA];
    __shared__ __half Ks[64 * ASA];
    __shared__ __half Vs[64 * ASA];
    __shared__ float  Mbs[MBTILE];

    const int bh = blockIdx.x;
    const int b = bh >> 4;
    const int h = bh & 15;
    const int tid = threadIdx.x;
    const int lane = tid & 31;
    const int w = tid >> 5;
    const float scale = 0.17677669529663689f;

    const uint32_t sQ = (uint32_t)__cvta_generic_to_shared(Qs);
    const uint32_t sK = (uint32_t)__cvta_generic_to_shared(Ks);
    const uint32_t sV = (uint32_t)__cvta_generic_to_shared(Vs);
    const uint32_t sM = (uint32_t)__cvta_generic_to_shared(Mbs);

    {
        const char* src = (const char*)(g_mb + (size_t)((b & (NWIN - 1)) * HEADS + h) * MBTILE);
        for (int i = tid; i < (MBTILE * 4) / 16; i += 128)
            cpasync16(sM + i * 16, src + i * 16);
    }

    {
        const __half* src = g_qkvh + (size_t)b * SW * (3 * DIMC) + h * HD;
#pragma unroll
        for (int i = 0; i < 2; i++) {
            const int e = tid + i * 128;
            const int row = e >> 2, seg = (e & 3) * 8;
            const uint32_t off = (uint32_t)(row * ASA + seg) * 2u;
            if (row < SW) {
                const __half* p = src + (size_t)row * (3 * DIMC) + seg;
                cpasync16(sQ + off, p);
                cpasync16(sK + off, p + DIMC);
                cpasync16(sV + off, p + 2 * DIMC);
            } else {
                const uint4 z = {0, 0, 0, 0};
                *(uint4*)&Qs[row * ASA + seg] = z;
                *(uint4*)&Ks[row * ASA + seg] = z;
                *(uint4*)&Vs[row * ASA + seg] = z;
            }
        }
    }
    asm volatile("cp.async.commit_group;");
    asm volatile("cp.async.wait_group 0;");
    __syncthreads();

    const int rowoff = ((lane >> 3) & 1) * 8 + (lane & 7);
    const unsigned aBase = (unsigned)((w * 16 + rowoff) * ASA + (lane >> 4) * 8);
    const unsigned bBase = (unsigned)((((lane >> 4) & 1) * 8 + (lane & 7)) * ASA
                                      + ((lane >> 3) & 1) * 8);

    float sc[8][4];
#pragma unroll
    for (int nb = 0; nb < 8; nb++)
#pragma unroll
        for (int r = 0; r < 4; r++) sc[nb][r] = 0.f;

#pragma unroll
    for (int ks = 0; ks < 2; ks++) {
        unsigned afr[4];
        ldsm4(afr[0], afr[1], afr[2], afr[3], sQ + (aBase + ks * 16) * 2u);
        unsigned bfr[8][2];
#pragma unroll
        for (int p = 0; p < 4; p++) {
            unsigned r0, r1, r2, r3;
            ldsm4(r0, r1, r2, r3, sK + ((unsigned)(p * 16 * ASA + ks * 16) + bBase) * 2u);
            bfr[2 * p][0] = r0;     bfr[2 * p][1] = r1;
            bfr[2 * p + 1][0] = r2; bfr[2 * p + 1][1] = r3;
        }
#pragma unroll
        for (int nb = 0; nb < 8; nb++) mma_f16(sc[nb], afr, bfr[nb]);
    }

    const int rA = w * 16 + (lane >> 2);
    const int rB = rA + 8;

    float mxA = -1e30f, mxB = -1e30f;
#pragma unroll
    for (int nb = 0; nb < 8; nb++) {
        const int c0 = nb * 8 + (lane & 3) * 2;
        const bool vA0 = (rA < SW) && (c0 < SW), vA1 = (rA < SW) && (c0 + 1 < SW);
        const bool vB0 = (rB < SW) && (c0 < SW), vB1 = (rB < SW) && (c0 + 1 < SW);
        sc[nb][0] = vA0 ? fmaf(sc[nb][0], scale, Mbs[rA * MBROW + c0])     : -1e30f;
        sc[nb][1] = vA1 ? fmaf(sc[nb][1], scale, Mbs[rA * MBROW + c0 + 1]) : -1e30f;
        sc[nb][2] = vB0 ? fmaf(sc[nb][2], scale, Mbs[rB * MBROW + c0])     : -1e30f;
        sc[nb][3] = vB1 ? fmaf(sc[nb][3], scale, Mbs[rB * MBROW + c0 + 1]) : -1e30f;
        mxA = fmaxf(mxA, fmaxf(sc[nb][0], sc[nb][1]));
        mxB = fmaxf(mxB, fmaxf(sc[nb][2], sc[nb][3]));
    }
    mxA = fmaxf(mxA, __shfl_xor_sync(0xFFFFFFFFu, mxA, 1));
    mxA = fmaxf(mxA, __shfl_xor_sync(0xFFFFFFFFu, mxA, 2));
    mxB = fmaxf(mxB, __shfl_xor_sync(0xFFFFFFFFu, mxB, 1));
    mxB = fmaxf(mxB, __shfl_xor_sync(0xFFFFFFFFu, mxB, 2));

    float sA = 0.f, sB = 0.f;
#pragma unroll
    for (int nb = 0; nb < 8; nb++) {
        sc[nb][0] = fast_exp(sc[nb][0] - mxA);
        sc[nb][1] = fast_exp(sc[nb][1] - mxA);
        sc[nb][2] = fast_exp(sc[nb][2] - mxB);
        sc[nb][3] = fast_exp(sc[nb][3] - mxB);
        sA += sc[nb][0] + sc[nb][1];
        sB += sc[nb][2] + sc[nb][3];
    }
    sA += __shfl_xor_sync(0xFFFFFFFFu, sA, 1);
    sA += __shfl_xor_sync(0xFFFFFFFFu, sA, 2);
    sB += __shfl_xor_sync(0xFFFFFFFFu, sB, 1);
    sB += __shfl_xor_sync(0xFFFFFFFFu, sB, 2);
    const float invA = __fdividef(1.f, sA);
    const float invB = __fdividef(1.f, sB);

    float o[4][4];
#pragma unroll
    for (int db = 0; db < 4; db++)
#pragma unroll
        for (int r = 0; r < 4; r++) o[db][r] = 0.f;

#pragma unroll
    for (int j = 0; j < 4; j++) {
        unsigned pf[4];
        pf[0] = packh2(sc[2 * j][0] * invA, sc[2 * j][1] * invA);
        pf[1] = packh2(sc[2 * j][2] * invB, sc[2 * j][3] * invB);
        pf[2] = packh2(sc[2 * j + 1][0] * invA, sc[2 * j + 1][1] * invA);
        pf[3] = packh2(sc[2 * j + 1][2] * invB, sc[2 * j + 1][3] * invB);

        const unsigned vrow = (unsigned)(16 * j + (lane & 7) + 8 * ((lane >> 3) & 1));
        unsigned vf[4][2];
#pragma unroll
        for (int nb2 = 0; nb2 < 2; nb2++) {
            unsigned r0, r1, r2, r3;
            uint32_t addr = sV + (vrow * ASA + nb2 * 16 + ((lane >> 4) & 1) * 8) * 2u;
            ldsm4t(r0, r1, r2, r3, addr);
            vf[2 * nb2][0] = r0;     vf[2 * nb2][1] = r1;
            vf[2 * nb2 + 1][0] = r2; vf[2 * nb2 + 1][1] = r3;
        }
#pragma unroll
        for (int db = 0; db < 4; db++) mma_f16(o[db], pf, vf[db]);
    }

    if (rA < SW) {
        __half* out = g_atth + ((size_t)(b * SW + rA)) * DIMC + h * HD;
#pragma unroll
        for (int db = 0; db < 4; db++)
            *(unsigned*)&out[db * 8 + (lane & 3) * 2] = packh2(o[db][0], o[db][1]);
    }
    if (rB < SW) {
        __half* out = g_atth + ((size_t)(b * SW + rB)) * DIMC + h * HD;
#pragma unroll
        for (int db = 0; db < 4; db++)
            *(unsigned*)&out[db * 8 + (lane & 3) * 2] = packh2(o[db][2], o[db][3]);
    }
}

// ---------------------------------------------------------------------------
extern "C" void kernel_launch(void* const* d_in, const int* in_sizes, int n_in,
                              void* d_out, int out_size) {
    const float* x          = (const float*)d_in[0];
    const float* mask       = (const float*)d_in[1];
    const float* qkv_w      = (const float*)d_in[2];
    const float* qkv_b      = (const float*)d_in[3];
    const float* proj_w     = (const float*)d_in[4];
    const float* proj_b     = (const float*)d_in[5];
    const float* bias_table = (const float*)d_in[6];
    const int*   rel_idx    = (const int*)d_in[7];

    static __half* qkvh_ptr = nullptr;
    static __half* atth_ptr = nullptr;
    static __half* xh_ptr = nullptr;
    static __half* wtqh_ptr = nullptr;
    static __half* wtph_ptr = nullptr;
    if (!qkvh_ptr) {
        cudaGetSymbolAddress((void**)&qkvh_ptr, g_qkvh);
        cudaGetSymbolAddress((void**)&atth_ptr, g_atth);
        cudaGetSymbolAddress((void**)&xh_ptr, g_xh);
        cudaGetSymbolAddress((void**)&wtqh_ptr, g_wtqh);
        cudaGetSymbolAddress((void**)&wtph_ptr, g_wtph);
        cudaFuncSetAttribute((const void*)gemm_f16_kernel<__half, DIMC>,
                             cudaFuncAttributeMaxDynamicSharedMemorySize, GEMM_SMEM);
        cudaFuncSetAttribute((const void*)gemm_f16_kernel<float, DIMC>,
                             cudaFuncAttributeMaxDynamicSharedMemorySize, GEMM_SMEM);
    }

    // 0) fused pre-pass
    prepass_kernel<<<NCVT + NTQ + NTP + NMB, 256>>>(
        (const float4*)x, qkv_w, proj_w, mask, bias_table, rel_idx);

    // 1) QKV projection -> fp16
    gemm_f16_kernel<__half, DIMC><<<dim3(3 * DIMC / 128, TOKENS / 128), 128, GEMM_SMEM>>>(
        xh_ptr, wtqh_ptr, qkv_b, qkvh_ptr, TOKENS, 3 * DIMC);

    // 2) Tensor-core windowed attention
    attn_mma_kernel<<<BWIN * HEADS, 128>>>();

    // 3) Output projection -> fp32 d_out
    gemm_f16_kernel<float, DIMC><<<dim3(DIMC / 128, TOKENS / 128), 128, GEMM_SMEM>>>(
        atth_ptr, wtph_ptr, proj_b, (float*)d_out, TOKENS, DIMC);
}